// round 1
// baseline (speedup 1.0000x reference)
#include <cuda_runtime.h>
#include <math.h>

// Problem constants (fixed by the dataset): N = 131072, D = 512, K = 256
#define DD 512
#define KK 256
#define TEMP 10.0f

// Normalized prototypes scratch (512 KB device global; no runtime alloc).
__device__ float g_pnorm[KK * DD];

// ---------------------------------------------------------------------------
// Kernel A: p_norm = prototypes / max(||row||, 1e-12)
// ---------------------------------------------------------------------------
__global__ void norm_protos_kernel(const float* __restrict__ p) {
    int k = blockIdx.x;
    float s = 0.f;
    for (int d = threadIdx.x; d < DD; d += 256) {
        float v = p[k * DD + d];
        s += v * v;
    }
    __shared__ float red[8];
    #pragma unroll
    for (int o = 16; o; o >>= 1) s += __shfl_xor_sync(0xffffffffu, s, o);
    if ((threadIdx.x & 31) == 0) red[threadIdx.x >> 5] = s;
    __syncthreads();
    if (threadIdx.x == 0) {
        float t = 0.f;
        #pragma unroll
        for (int i = 0; i < 8; ++i) t += red[i];
        red[0] = 1.0f / fmaxf(sqrtf(t), 1e-12f);
    }
    __syncthreads();
    float inv = red[0];
    for (int d = threadIdx.x; d < DD; d += 256) {
        g_pnorm[k * DD + d] = p[k * DD + d] * inv;
    }
}

// ---------------------------------------------------------------------------
// Kernel B: fused  normalize(z) -> sims GEMM -> sparsemax -> recon GEMM
//           -> residual.  One CTA handles TM=32 rows.
//
// Shared layout (dynamic, 71296 B -> 2 CTAs/SM):
//   zch [32][33]   : z_norm d-chunk for GEMM1           (1056 f)
//   ssh [32][260]  : logits, then weights               (8320 f)
//   psh            : union of GEMM1 p-chunk [256][33] and
//                    GEMM2 p-chunk [32][260]            (8448 f)
// ---------------------------------------------------------------------------
__global__ __launch_bounds__(256, 2)
void fused_kernel(const float* __restrict__ z, float* __restrict__ out, int N) {
    extern __shared__ float sm[];
    float* zch = sm;                  // 32*33
    float* ssh = sm + 32 * 33;        // 32*260
    float* psh = ssh + 32 * 260;      // 8448
    __shared__ float snorm[32];

    const int tid  = threadIdx.x;
    const int lane = tid & 31;
    const int wid  = tid >> 5;
    const int kt   = lane;            // k/d sub-index within register tile
    const int mt4  = wid * 4;         // 4 rows owned by this warp
    const size_t row0 = (size_t)blockIdx.x * 32;
    const size_t woff = (size_t)N * 512;   // weights offset in out
    const size_t roff = (size_t)N * 768;   // residual offset in out

    // ---------------- Phase 0: per-row 1/||z|| ----------------
    #pragma unroll 1
    for (int r = wid; r < 32; r += 8) {
        float s = 0.f;
        #pragma unroll
        for (int j = 0; j < 16; ++j) {
            float v = z[(row0 + r) * 512 + lane + 32 * j];
            s += v * v;
        }
        #pragma unroll
        for (int o = 16; o; o >>= 1) s += __shfl_xor_sync(0xffffffffu, s, o);
        if (lane == 0) snorm[r] = 1.0f / fmaxf(sqrtf(s), 1e-12f);
    }
    __syncthreads();

    // ---------------- GEMM1: logits[32][256] = 10 * z_norm @ p_norm^T ------
    float acc[4][8];
    #pragma unroll
    for (int i = 0; i < 4; ++i)
        #pragma unroll
        for (int j = 0; j < 8; ++j) acc[i][j] = 0.f;

    #pragma unroll 1
    for (int dc = 0; dc < 16; ++dc) {
        if (dc) __syncthreads();
        // z chunk [32][32], normalized on the fly
        #pragma unroll
        for (int t = 0; t < 4; ++t) {
            int idx = tid + 256 * t;
            int m = idx >> 5, d = idx & 31;
            zch[m * 33 + d] = z[(row0 + m) * 512 + dc * 32 + d] * snorm[m];
        }
        // p chunk [256][32]
        #pragma unroll
        for (int t = 0; t < 32; ++t) {
            int idx = tid + 256 * t;
            int k = idx >> 5, d = idx & 31;
            psh[k * 33 + d] = g_pnorm[k * 512 + dc * 32 + d];
        }
        __syncthreads();
        #pragma unroll 8
        for (int d = 0; d < 32; ++d) {
            float a0 = zch[(mt4 + 0) * 33 + d];
            float a1 = zch[(mt4 + 1) * 33 + d];
            float a2 = zch[(mt4 + 2) * 33 + d];
            float a3 = zch[(mt4 + 3) * 33 + d];
            #pragma unroll
            for (int j = 0; j < 8; ++j) {
                float b = psh[(kt + 32 * j) * 33 + d];
                acc[0][j] += a0 * b;
                acc[1][j] += a1 * b;
                acc[2][j] += a2 * b;
                acc[3][j] += a3 * b;
            }
        }
    }
    __syncthreads();
    #pragma unroll
    for (int i = 0; i < 4; ++i)
        #pragma unroll
        for (int j = 0; j < 8; ++j)
            ssh[(mt4 + i) * 260 + kt + 32 * j] = acc[i][j] * TEMP;
    __syncthreads();

    // ---------------- Sparsemax (exact, sort-free Michelot fixed point) ----
    // warp `wid` owns rows mt4..mt4+3; 8 logits per lane.
    #pragma unroll 1
    for (int r4 = 0; r4 < 4; ++r4) {
        int r = mt4 + r4;
        float v[8];
        #pragma unroll
        for (int j = 0; j < 8; ++j) v[j] = ssh[r * 260 + lane + 32 * j];
        float sum = 0.f;
        #pragma unroll
        for (int j = 0; j < 8; ++j) sum += v[j];
        #pragma unroll
        for (int o = 16; o; o >>= 1) sum += __shfl_xor_sync(0xffffffffu, sum, o);
        float cnt = 256.f;
        float tau = (sum - 1.0f) / cnt;
        for (int it = 0; it < 256; ++it) {
            float ns = 0.f, nc = 0.f;
            #pragma unroll
            for (int j = 0; j < 8; ++j) {
                if (v[j] > tau) { ns += v[j]; nc += 1.f; }
            }
            #pragma unroll
            for (int o = 16; o; o >>= 1) {
                ns += __shfl_xor_sync(0xffffffffu, ns, o);
                nc += __shfl_xor_sync(0xffffffffu, nc, o);
            }
            if (nc == cnt) break;       // support stable -> tau exact
            cnt = nc;
            tau = (ns - 1.0f) / nc;
        }
        size_t wbase = woff + (row0 + r) * 256;
        #pragma unroll
        for (int j = 0; j < 8; ++j) {
            float w = fmaxf(v[j] - tau, 0.f);
            ssh[r * 260 + lane + 32 * j] = w;   // reuse as GEMM2 A-operand
            out[wbase + lane + 32 * j] = w;     // weights output
        }
    }
    __syncthreads();

    // ---------------- GEMM2: z_recon[32][512] = weights @ p_norm -----------
    // two d-halves of 256 columns each; accumulate over k in chunks of 32.
    #pragma unroll 1
    for (int h = 0; h < 2; ++h) {
        float acc2[4][8];
        #pragma unroll
        for (int i = 0; i < 4; ++i)
            #pragma unroll
            for (int j = 0; j < 8; ++j) acc2[i][j] = 0.f;

        #pragma unroll 1
        for (int kc = 0; kc < 8; ++kc) {
            __syncthreads();
            #pragma unroll
            for (int t = 0; t < 32; ++t) {
                int idx = tid + 256 * t;
                int kk = idx >> 8, dd = idx & 255;
                psh[kk * 260 + dd] = g_pnorm[(kc * 32 + kk) * 512 + h * 256 + dd];
            }
            __syncthreads();
            #pragma unroll 8
            for (int kk = 0; kk < 32; ++kk) {
                float a0 = ssh[(mt4 + 0) * 260 + kc * 32 + kk];
                float a1 = ssh[(mt4 + 1) * 260 + kc * 32 + kk];
                float a2 = ssh[(mt4 + 2) * 260 + kc * 32 + kk];
                float a3 = ssh[(mt4 + 3) * 260 + kc * 32 + kk];
                #pragma unroll
                for (int j = 0; j < 8; ++j) {
                    float b = psh[kk * 260 + kt + 32 * j];
                    acc2[0][j] += a0 * b;
                    acc2[1][j] += a1 * b;
                    acc2[2][j] += a2 * b;
                    acc2[3][j] += a3 * b;
                }
            }
        }
        // epilogue: recon + residual (re-read z, L1/L2 hot)
        #pragma unroll
        for (int i = 0; i < 4; ++i) {
            size_t rg = row0 + mt4 + i;
            float inv = snorm[mt4 + i];
            #pragma unroll
            for (int j = 0; j < 8; ++j) {
                int d = h * 256 + kt + 32 * j;
                float rec = acc2[i][j];
                float zn  = z[rg * 512 + d] * inv;
                out[rg * 512 + d]        = rec;        // z_recon
                out[roff + rg * 512 + d] = zn - rec;   // residual
            }
        }
    }
}

// ---------------------------------------------------------------------------
extern "C" void kernel_launch(void* const* d_in, const int* in_sizes, int n_in,
                              void* d_out, int out_size) {
    const float* z = (const float*)d_in[0];        // [N, 512]
    const float* p = (const float*)d_in[1];        // [256, 512]
    float* out = (float*)d_out;                    // [N*512 | N*256 | N*512]
    int N = in_sizes[0] / DD;

    const int smem = (32 * 33 + 32 * 260 + 8448) * (int)sizeof(float); // 71296
    cudaFuncSetAttribute(fused_kernel,
                         cudaFuncAttributeMaxDynamicSharedMemorySize, smem);

    norm_protos_kernel<<<KK, 256>>>(p);
    fused_kernel<<<N / 32, 256, smem>>>(z, out, N);
}